// round 2
// baseline (speedup 1.0000x reference)
#include <cuda_runtime.h>
#include <cuda_bf16.h>

// DCN cross network, fully fused over L=4 layers.
// x: (B=16384, D=1024) fp32; weights: (4, 1024); biases: (4, 1024).
// x_{l+1} = x0 * (x_l . w_l) + b_l + x_l
//
// One CTA per row. 256 threads, each owns a float4 (4 elems) of the row.
// x0 and x_c live in registers for all 4 layers; only traffic is one read
// of x and one write of out (128 MiB total) -> HBM-bound, ~20 us target.

#define B_ROWS 16384
#define D_DIM  1024
#define L_LAYERS 4
#define THREADS 256

__global__ __launch_bounds__(THREADS, 8)
void dcn_cross_kernel(const float* __restrict__ x,
                      const float* __restrict__ w,
                      const float* __restrict__ b,
                      float* __restrict__ out) {
    const int row = blockIdx.x;
    const int t   = threadIdx.x;          // 0..255
    const int lane = t & 31;
    const int wid  = t >> 5;              // 0..7

    __shared__ float s_warp[8];
    __shared__ float s_bcast;

    const float4* xrow = reinterpret_cast<const float4*>(x + (size_t)row * D_DIM);
    float4 x0 = xrow[t];
    float4 xc = x0;

    #pragma unroll
    for (int l = 0; l < L_LAYERS; l++) {
        const float4 wl = reinterpret_cast<const float4*>(w + l * D_DIM)[t];

        // partial dot over this thread's 4 elements
        float p = xc.x * wl.x + xc.y * wl.y + xc.z * wl.z + xc.w * wl.w;

        // warp reduce
        #pragma unroll
        for (int o = 16; o > 0; o >>= 1)
            p += __shfl_down_sync(0xffffffffu, p, o);
        if (lane == 0) s_warp[wid] = p;
        __syncthreads();

        // cross-warp reduce (8 partials) in warp 0
        if (t < 8) {
            float s = s_warp[t];
            #pragma unroll
            for (int o = 4; o > 0; o >>= 1)
                s += __shfl_down_sync(0x000000ffu, s, o);
            if (t == 0) s_bcast = s;
        }
        __syncthreads();

        const float s = s_bcast;
        const float4 bl = reinterpret_cast<const float4*>(b + l * D_DIM)[t];

        xc.x = fmaf(x0.x, s, bl.x + xc.x);
        xc.y = fmaf(x0.y, s, bl.y + xc.y);
        xc.z = fmaf(x0.z, s, bl.z + xc.z);
        xc.w = fmaf(x0.w, s, bl.w + xc.w);
    }

    reinterpret_cast<float4*>(out + (size_t)row * D_DIM)[t] = xc;
}

extern "C" void kernel_launch(void* const* d_in, const int* in_sizes, int n_in,
                              void* d_out, int out_size) {
    const float* x = (const float*)d_in[0];
    const float* w = (const float*)d_in[1];
    const float* b = (const float*)d_in[2];
    float* out = (float*)d_out;
    dcn_cross_kernel<<<B_ROWS, THREADS>>>(x, w, b, out);
}

// round 3
// speedup vs baseline: 1.1618x; 1.1618x over previous
#include <cuda_runtime.h>
#include <cuda_bf16.h>

// DCN cross network, fused over L=4 layers, R rows per CTA.
// x: (16384, 1024) fp32; weights/biases: (4, 1024).
// x_{l+1} = x0 * (x_l . w_l) + b_l + x_l
//
// R2 insight: w/b re-load per CTA made the kernel L1-bound (78% L1, 24% DRAM).
// Now each CTA loads w/b into REGISTERS once and processes R=8 rows,
// cutting per-row global ops from 10 to 3 (x load, out store).
// Next-row x is prefetched before the layer loop to hide DRAM latency
// at the reduced (~4 CTA/SM) occupancy.

#define B_ROWS   16384
#define D_DIM    1024
#define L_LAYERS 4
#define THREADS  256          // 1024 floats / 4 per thread
#define R_ROWS   8            // rows per CTA -> grid = 2048

__global__ __launch_bounds__(THREADS, 4)
void dcn_cross_kernel(const float4* __restrict__ x,
                      const float4* __restrict__ w,
                      const float4* __restrict__ b,
                      float4* __restrict__ out) {
    const int t    = threadIdx.x;        // 0..255
    const int lane = t & 31;
    const int wid  = t >> 5;             // 0..7

    // per-layer partial buffers: only ONE barrier per layer needed
    // (write -> sync -> broadcast-read; next write to this buffer is
    // separated by the other layers' barriers)
    __shared__ float s_warp[L_LAYERS][8];

    // weights + biases register-resident for the whole CTA lifetime
    float4 W[L_LAYERS], Bv[L_LAYERS];
    #pragma unroll
    for (int l = 0; l < L_LAYERS; l++) {
        W[l]  = w[l * THREADS + t];
        Bv[l] = b[l * THREADS + t];
    }

    const size_t base = (size_t)blockIdx.x * R_ROWS * THREADS + t;

    float4 xin = x[base];                       // prefetch row 0

    #pragma unroll 1
    for (int r = 0; r < R_ROWS; r++) {
        const float4 x0 = xin;
        if (r + 1 < R_ROWS)
            xin = x[base + (size_t)(r + 1) * THREADS];   // prefetch next row

        float4 xc = x0;

        #pragma unroll
        for (int l = 0; l < L_LAYERS; l++) {
            // partial dot over this thread's 4 elements
            float p = xc.x * W[l].x + xc.y * W[l].y
                    + xc.z * W[l].z + xc.w * W[l].w;

            // warp reduce
            #pragma unroll
            for (int o = 16; o > 0; o >>= 1)
                p += __shfl_down_sync(0xffffffffu, p, o);
            if (lane == 0) s_warp[l][wid] = p;
            __syncthreads();

            // every thread sums the 8 warp partials (broadcast LDS)
            float s = 0.f;
            #pragma unroll
            for (int k = 0; k < 8; k++) s += s_warp[l][k];

            xc.x = fmaf(x0.x, s, Bv[l].x + xc.x);
            xc.y = fmaf(x0.y, s, Bv[l].y + xc.y);
            xc.z = fmaf(x0.z, s, Bv[l].z + xc.z);
            xc.w = fmaf(x0.w, s, Bv[l].w + xc.w);
        }

        out[base + (size_t)r * THREADS] = xc;
    }
}

extern "C" void kernel_launch(void* const* d_in, const int* in_sizes, int n_in,
                              void* d_out, int out_size) {
    const float4* x = (const float4*)d_in[0];
    const float4* w = (const float4*)d_in[1];
    const float4* b = (const float4*)d_in[2];
    float4* o = (float4*)d_out;
    dcn_cross_kernel<<<B_ROWS / R_ROWS, THREADS>>>(x, w, b, o);
}